// round 11
// baseline (speedup 1.0000x reference)
#include <cuda_runtime.h>
#include <cuda_bf16.h>
#include <cstdint>
#include <cstddef>

// ---------------------------------------------------------------------------
// Problem dims
// ---------------------------------------------------------------------------
#define EMB    1024
#define PAR    4096
#define MROWS  8192          // 4 * 2048

// ---------------------------------------------------------------------------
// GEMM tiling (mma.sync HMMA path — tcgen05 is not compilable on the
// harness's compute_103 PTX target)
// ---------------------------------------------------------------------------
#define BM       128
#define BN       128
#define KC       64          // k per smem stage (64 bf16 = 128B rows, SW128)
#define STAGES   3
#define GTHREADS 256

#define A_STAGE_BYTES (BM * 128)     // 16384
#define B_STAGE_BYTES (BN * 128)     // 16384
#define SM_A     0
#define SM_B     (STAGES * A_STAGE_BYTES)                 // 49152
#define SM_TOTAL (SM_B + STAGES * B_STAGE_BYTES)          // 98304

// SW128 swizzle (Swizzle<3,4,3>), 16B-granular
#define SWZ(o) ((o) ^ ((((uint32_t)(o)) >> 3) & 0x70))

// ---------------------------------------------------------------------------
// Device scratch (static globals; no allocation anywhere)
// ---------------------------------------------------------------------------
__device__ __nv_bfloat16 g_xhi [(size_t)MROWS * EMB];
__device__ __nv_bfloat16 g_xlo [(size_t)MROWS * EMB];
__device__ __nv_bfloat16 g_Khi [(size_t)PAR   * EMB];
__device__ __nv_bfloat16 g_Klo [(size_t)PAR   * EMB];
__device__ __nv_bfloat16 g_VThi[(size_t)EMB   * PAR];
__device__ __nv_bfloat16 g_VTlo[(size_t)EMB   * PAR];
__device__ float         g_S   [(size_t)MROWS * PAR];   // fp32 scores, 128 MB
__device__ __nv_bfloat16 g_Ahi [(size_t)MROWS * PAR];
__device__ __nv_bfloat16 g_Alo [(size_t)MROWS * PAR];

// ---------------------------------------------------------------------------
// PTX helpers (family-portable only: cp.async / ldmatrix / mma.sync)
// ---------------------------------------------------------------------------
__device__ __forceinline__ uint32_t smem_u32(const void* p) {
    uint32_t a;
    asm("{ .reg .u64 t; cvta.to.shared.u64 t, %1; cvt.u32.u64 %0, t; }" : "=r"(a) : "l"(p));
    return a;
}

__device__ __forceinline__ void cpasync16(uint32_t saddr, const void* gaddr) {
    asm volatile("cp.async.cg.shared.global [%0], [%1], 16;" :: "r"(saddr), "l"(gaddr) : "memory");
}
#define CP_COMMIT() asm volatile("cp.async.commit_group;" ::: "memory")
#define CP_WAIT(n)  asm volatile("cp.async.wait_group %0;" :: "n"(n) : "memory")

__device__ __forceinline__ void ldsm4(uint32_t* r, uint32_t addr) {
    asm volatile("ldmatrix.sync.aligned.m8n8.x4.shared.b16 {%0,%1,%2,%3}, [%4];"
                 : "=r"(r[0]), "=r"(r[1]), "=r"(r[2]), "=r"(r[3]) : "r"(addr));
}

__device__ __forceinline__ void mma_bf16(float* d, const uint32_t* a, const uint32_t* b) {
    asm volatile(
        "mma.sync.aligned.m16n8k16.row.col.f32.bf16.bf16.f32 "
        "{%0,%1,%2,%3}, {%4,%5,%6,%7}, {%8,%9}, {%0,%1,%2,%3};"
        : "+f"(d[0]), "+f"(d[1]), "+f"(d[2]), "+f"(d[3])
        : "r"(a[0]), "r"(a[1]), "r"(a[2]), "r"(a[3]), "r"(b[0]), "r"(b[1]));
}

// ---------------------------------------------------------------------------
// Split kernels (bf16 hi/lo decomposition)
// ---------------------------------------------------------------------------
__global__ void split_kernel(const float* __restrict__ in, int which, int n) {
    __nv_bfloat16 *hi, *lo;
    float scale;
    if (which == 0) { hi = g_xhi; lo = g_xlo; scale = 0.03125f; }  // 1024^-0.5 exact
    else            { hi = g_Khi; lo = g_Klo; scale = 1.0f; }
    int i = blockIdx.x * blockDim.x + threadIdx.x;
    if (i < n) {
        float v = in[i] * scale;
        __nv_bfloat16 h = __float2bfloat16(v);
        hi[i] = h;
        lo[i] = __float2bfloat16(v - __bfloat162float(h));
    }
}

// V [PAR, EMB] -> VT hi/lo [EMB, PAR]
__global__ void splitV_kernel(const float* __restrict__ V) {
    __shared__ float tile[32][33];
    int e0 = blockIdx.x * 32, p0 = blockIdx.y * 32;
    int tx = threadIdx.x, ty = threadIdx.y;
    for (int r = ty; r < 32; r += 8)
        tile[r][tx] = V[(size_t)(p0 + r) * EMB + e0 + tx];
    __syncthreads();
    for (int r = ty; r < 32; r += 8) {
        float v = tile[tx][r];                       // = V[p0+tx][e0+r]
        size_t idx = (size_t)(e0 + r) * PAR + p0 + tx;
        __nv_bfloat16 h = __float2bfloat16(v);
        g_VThi[idx] = h;
        g_VTlo[idx] = __float2bfloat16(v - __bfloat162float(h));
    }
}

// ---------------------------------------------------------------------------
// Row softmax over S[row, 0:4096] -> attn hi/lo bf16
// ---------------------------------------------------------------------------
__global__ __launch_bounds__(256) void softmax_kernel() {
    __shared__ float red[8];
    const int row = blockIdx.x;
    const float* srow = g_S + (size_t)row * PAR;
    const int t = threadIdx.x;

    float v[16];
    float m = -1e30f;
#pragma unroll
    for (int i = 0; i < 16; i++) { v[i] = srow[t + i * 256]; m = fmaxf(m, v[i]); }
#pragma unroll
    for (int o = 16; o; o >>= 1) m = fmaxf(m, __shfl_xor_sync(~0u, m, o));
    if ((t & 31) == 0) red[t >> 5] = m;
    __syncthreads();
    m = red[0];
#pragma unroll
    for (int w = 1; w < 8; w++) m = fmaxf(m, red[w]);

    float sum = 0.f;
#pragma unroll
    for (int i = 0; i < 16; i++) { v[i] = __expf(v[i] - m); sum += v[i]; }
#pragma unroll
    for (int o = 16; o; o >>= 1) sum += __shfl_xor_sync(~0u, sum, o);
    __syncthreads();
    if ((t & 31) == 0) red[t >> 5] = sum;
    __syncthreads();
    sum = 0.f;
#pragma unroll
    for (int w = 0; w < 8; w++) sum += red[w];
    const float inv = 1.0f / sum;

#pragma unroll
    for (int i = 0; i < 16; i++) {
        float a = v[i] * inv;
        __nv_bfloat16 h = __float2bfloat16(a);
        size_t idx = (size_t)row * PAR + t + i * 256;
        g_Ahi[idx] = h;
        g_Alo[idx] = __float2bfloat16(a - __bfloat162float(h));
    }
}

// ---------------------------------------------------------------------------
// HMMA GEMM: D[M,N] = sum over 3 segments of A_seg[M,Kseg] @ B_seg[N,Kseg]^T
//   which == 0: S = x3 @ K3^T      (Kseg=1024, Ntot=4096, C=g_S)
//   which == 1: out = A3 @ VT3^T   (Kseg=4096, Ntot=1024, C=outp)
// BM=BN=128, KC=64, 3-stage cp.async pipe, 8 warps (2m x 4n), warp tile 64x32.
// ---------------------------------------------------------------------------
__global__ __launch_bounds__(GTHREADS, 2) void gemm_kernel(int which, float* __restrict__ outp) {
    extern __shared__ char smem[];
    const uint32_t sbase = smem_u32(smem);
    const int tid  = threadIdx.x;
    const int wid  = tid >> 5;
    const int lane = tid & 31;
    const int wm   = wid & 1;     // 2 warps along M (64 rows each)
    const int wn   = wid >> 1;    // 4 warps along N (32 cols each)

    const __nv_bfloat16 *Aseg[3], *Bseg[3];
    float* C;
    int Kseg, Ntot;
    if (which == 0) {
        Aseg[0] = g_xhi; Aseg[1] = g_xlo; Aseg[2] = g_xhi;
        Bseg[0] = g_Khi; Bseg[1] = g_Khi; Bseg[2] = g_Klo;
        C = g_S; Kseg = EMB; Ntot = PAR;
    } else {
        Aseg[0] = g_Ahi;  Aseg[1] = g_Alo;  Aseg[2] = g_Ahi;
        Bseg[0] = g_VThi; Bseg[1] = g_VThi; Bseg[2] = g_VTlo;
        C = outp; Kseg = PAR; Ntot = EMB;
    }
    const int it_per_seg = Kseg / KC;
    const int nk = 3 * it_per_seg;
    const int row0 = blockIdx.y * BM;
    const int col0 = blockIdx.x * BN;

    // ldmatrix lane-derived offsets
    const uint32_t a_lrow = lane & 15;
    const uint32_t a_koff = (lane >> 4) * 16;                       // bytes
    const uint32_t b_lrow = ((lane >> 4) << 3) | (lane & 7);
    const uint32_t b_koff = ((lane >> 3) & 1) * 16;                 // bytes

    float acc[4][4][4];
#pragma unroll
    for (int a = 0; a < 4; a++)
#pragma unroll
        for (int b = 0; b < 4; b++)
#pragma unroll
            for (int c = 0; c < 4; c++) acc[a][b][c] = 0.f;

    // Per-stage loader: A/B tiles each 128x64 bf16 = 1024 x 16B chunks
    auto issue_stage = [&](int it, int stage) {
        const int seg = it / it_per_seg;
        const int kk = (it - seg * it_per_seg) * KC;
        const __nv_bfloat16* Ag = Aseg[seg];
        const __nv_bfloat16* Bg = Bseg[seg];
        const uint32_t sa = sbase + SM_A + stage * A_STAGE_BYTES;
        const uint32_t sb = sbase + SM_B + stage * B_STAGE_BYTES;
#pragma unroll
        for (int cc = 0; cc < 4; cc++) {
            int c = tid + cc * GTHREADS;
            int r = c >> 3, j = c & 7;
            cpasync16(sa + SWZ(r * 128 + j * 16),
                      Ag + (size_t)(row0 + r) * Kseg + kk + j * 8);
        }
#pragma unroll
        for (int cc = 0; cc < 4; cc++) {
            int c = tid + cc * GTHREADS;
            int r = c >> 3, j = c & 7;
            cpasync16(sb + SWZ(r * 128 + j * 16),
                      Bg + (size_t)(col0 + r) * Kseg + kk + j * 8);
        }
        CP_COMMIT();
    };

    auto compute_stage = [&](int st) {
        const uint32_t sa = sbase + SM_A + st * A_STAGE_BYTES;
        const uint32_t sb = sbase + SM_B + st * B_STAGE_BYTES;
#pragma unroll
        for (int kk = 0; kk < 4; kk++) {          // 4 x k16 per KC=64 stage
            uint32_t afr[4][4];
#pragma unroll
            for (int mf = 0; mf < 4; mf++) {
                uint32_t off = (uint32_t)(wm * 64 + mf * 16 + a_lrow) * 128
                             + kk * 32 + a_koff;
                ldsm4(afr[mf], sa + SWZ(off));
            }
            uint32_t bfr[2][4];
#pragma unroll
            for (int np = 0; np < 2; np++) {
                uint32_t off = (uint32_t)(wn * 32 + np * 16 + b_lrow) * 128
                             + kk * 32 + b_koff;
                ldsm4(bfr[np], sb + SWZ(off));
            }
#pragma unroll
            for (int mf = 0; mf < 4; mf++)
#pragma unroll
                for (int nf = 0; nf < 4; nf++)
                    mma_bf16(acc[mf][nf], afr[mf], &bfr[nf >> 1][(nf & 1) * 2]);
        }
    };

    // Prologue: stages 0,1 in flight
    issue_stage(0, 0);
    issue_stage(1, 1);

    for (int i = 0; i < nk; ++i) {
        if (i < nk - 2) CP_WAIT(1); else CP_WAIT(0);
        __syncthreads();
        const int ip = i + 2;
        if (ip < nk) issue_stage(ip, ip % STAGES);
        compute_stage(i % STAGES);
    }

    // Epilogue: fp32 accumulators -> C (float2 stores)
    const int tq = lane >> 2;
    const int tr = lane & 3;
#pragma unroll
    for (int mf = 0; mf < 4; mf++) {
        const int r0 = row0 + wm * 64 + mf * 16 + tq;
#pragma unroll
        for (int nf = 0; nf < 4; nf++) {
            const int c = col0 + wn * 32 + nf * 8 + tr * 2;
            float2 v0 = make_float2(acc[mf][nf][0], acc[mf][nf][1]);
            float2 v1 = make_float2(acc[mf][nf][2], acc[mf][nf][3]);
            *reinterpret_cast<float2*>(C + (size_t)r0 * Ntot + c)       = v0;
            *reinterpret_cast<float2*>(C + (size_t)(r0 + 8) * Ntot + c) = v1;
        }
    }
}

// ---------------------------------------------------------------------------
// Launch: split -> GEMM1 -> softmax -> GEMM2  (all default stream, capturable)
// ---------------------------------------------------------------------------
extern "C" void kernel_launch(void* const* d_in, const int* in_sizes, int n_in,
                              void* d_out, int out_size) {
    const float* x = (const float*)d_in[0];
    const float* K = (const float*)d_in[1];
    const float* V = (const float*)d_in[2];
    float* out = (float*)d_out;

    cudaFuncSetAttribute(gemm_kernel, cudaFuncAttributeMaxDynamicSharedMemorySize, SM_TOTAL);

    const int nx = MROWS * EMB;   // 8388608
    const int nK = PAR * EMB;     // 4194304
    split_kernel<<<(nx + 255) / 256, 256>>>(x, 0, nx);
    split_kernel<<<(nK + 255) / 256, 256>>>(K, 1, nK);
    splitV_kernel<<<dim3(EMB / 32, PAR / 32), dim3(32, 8)>>>(V);

    gemm_kernel<<<dim3(PAR / BN, MROWS / BM), GTHREADS, SM_TOTAL>>>(0, nullptr);

    softmax_kernel<<<MROWS, 256>>>();

    gemm_kernel<<<dim3(EMB / BN, MROWS / BM), GTHREADS, SM_TOTAL>>>(1, out);
}